// round 16
// baseline (speedup 1.0000x reference)
#include <cuda_runtime.h>
#include <math.h>
#include <stdint.h>

#define NB 8
#define NTOK 4096
#define NC 256
#define NHEAD 8
#define HD 32
#define RDIM 64
#define TILE 16
#define NPART 32

// Packed dual-fp32 FMA (sm_103a): one issue slot, two fp32 FMAs, bit-exact.
__device__ __forceinline__ float2 ffma2(float2 a, float2 b, float2 c) {
    unsigned long long A, B, C, D;
    A = *(unsigned long long*)&a;
    B = *(unsigned long long*)&b;
    C = *(unsigned long long*)&c;
    asm("fma.rn.f32x2 %0, %1, %2, %3;" : "=l"(D) : "l"(A), "l"(B), "l"(C));
    return *(float2*)&D;
}

__device__ __forceinline__ void cpasync16(void* smem_dst, const void* gsrc) {
    unsigned int s = (unsigned int)__cvta_generic_to_shared(smem_dst);
    asm volatile("cp.async.cg.shared.global [%0], [%1], 16;" :: "r"(s), "l"(gsrc) : "memory");
}

// Scratch (device globals: allocation is forbidden)
__device__ float g_part[NPART * NB * NHEAD * HD * HD];   // 8 MB partial kv
__device__ float g_parts[NPART * NB * NHEAD * HD];
__device__ float g_kv[NB * NHEAD * HD * HD];
__device__ float g_ksum[NB * NHEAD * HD];
__device__ float g_alpha[NB * NTOK];

// ---------------------------------------------------------------------------
// k_alpha: per-token focusing norm ratio for q. Warp = token.
// ---------------------------------------------------------------------------
__global__ __launch_bounds__(256) void k_alpha(
    const float* __restrict__ qkv,
    const float* __restrict__ scale)
{
    __shared__ float s_isc[NC];
    const int tid  = threadIdx.x;
    const int wid  = tid >> 5;
    const int lane = tid & 31;
    const int b    = blockIdx.y;

    s_isc[tid] = 1.f / log1pf(expf(scale[tid]));
    __syncthreads();

    const int i = blockIdx.x * 8 + wid;
    const float* qb = qkv + (size_t)b * NTOK * NC + (size_t)i * NC;

    const float4 qA = ((const float4*)qb)[lane];
    const float4 qB = ((const float4*)qb)[lane + 32];
    const float4 iA = ((const float4*)s_isc)[lane];
    const float4 iB = ((const float4*)s_isc)[lane + 32];

    float s2 = 0.f, s6 = 0.f;
#define FOC(qc, ic)                                         \
    {                                                       \
        float t = (fmaxf(qc, 0.f) + 1e-6f) * ic;            \
        s2 += t * t;                                        \
        float tc = t * t * t; s6 += tc * tc;                \
    }
    FOC(qA.x, iA.x) FOC(qA.y, iA.y) FOC(qA.z, iA.z) FOC(qA.w, iA.w)
    FOC(qB.x, iB.x) FOC(qB.y, iB.y) FOC(qB.z, iB.z) FOC(qB.w, iB.w)
#undef FOC

#pragma unroll
    for (int off = 16; off; off >>= 1) {
        s2 += __shfl_xor_sync(0xffffffffu, s2, off);
        s6 += __shfl_xor_sync(0xffffffffu, s6, off);
    }
    if (lane == 0) g_alpha[b * NTOK + i] = sqrtf(s2 / s6);
}

// ---------------------------------------------------------------------------
// k_stats: cp.async double-buffered pipeline, partial outputs (R14 version).
// ---------------------------------------------------------------------------
#define ST_F4   1024                    // float4 per array per buffer (16 tok x 64)
#define SMEM_STATS ((6 * ST_F4 + 64) * 16)   // 2 bufs x 3 arrays + isc = 99328 B

__global__ __launch_bounds__(512, 2) void k_stats(
    const float* __restrict__ qkv,
    const float* __restrict__ pos,
    const float* __restrict__ scale)
{
    extern __shared__ float4 smem4[];
    float4* sK = smem4;                  // [2][ST_F4]  (k3 written in place)
    float4* sP = smem4 + 2 * ST_F4;
    float4* sV = smem4 + 4 * ST_F4;
    float*  s_isc = (float*)(smem4 + 6 * ST_F4);

    const int tid  = threadIdx.x;
    const int wid  = tid >> 5;
    const int lane = tid & 31;
    const int b    = blockIdx.y;
    const int bx   = blockIdx.x;

    if (tid < NC) s_isc[tid] = 1.f / log1pf(expf(scale[tid]));

    const float* kb = qkv + ((size_t)NB + b) * NTOK * NC;
    const float* vb = qkv + ((size_t)2 * NB + b) * NTOK * NC;

    const int h    = wid >> 1;
    const int half = wid & 1;
    const int d    = lane;

    float2 acc2[8];
#pragma unroll
    for (int e = 0; e < 8; ++e) acc2[e] = make_float2(0.f, 0.f);
    float accs = 0.f;

    const int i0 = bx * (NTOK / NPART);          // 128 tokens per block

#define STAGE(it, bufi)                                                     \
    {                                                                       \
        _Pragma("unroll")                                                   \
        for (int u = 0; u < 2; ++u) {                                       \
            const int idx = tid + u * 512;                                  \
            const int row = idx >> 6, col4 = idx & 63;                      \
            const size_t g = (size_t)(i0 + (it) * 16 + row) * NC + col4 * 4;\
            cpasync16(&sK[(bufi) * ST_F4 + idx], kb + g);                   \
            cpasync16(&sP[(bufi) * ST_F4 + idx], pos + g);                  \
            cpasync16(&sV[(bufi) * ST_F4 + idx], vb + g);                   \
        }                                                                   \
        asm volatile("cp.async.commit_group;" ::: "memory");                \
    }

    STAGE(0, 0)
    __syncthreads();                              // s_isc visible
    const float4 iscA = ((const float4*)s_isc)[lane];
    const float4 iscB = ((const float4*)s_isc)[lane + 32];

    for (int it = 0; it < 8; ++it) {
        const int cur = it & 1;
        if (it < 7) {
            STAGE(it + 1, cur ^ 1)
            asm volatile("cp.async.wait_group 1;" ::: "memory");
        } else {
            asm volatile("cp.async.wait_group 0;" ::: "memory");
        }
        __syncthreads();                          // staged data visible to all

        {
            const float4 kA = sK[cur * ST_F4 + wid * 64 + lane];
            const float4 kB = sK[cur * ST_F4 + wid * 64 + lane + 32];
            const float4 pA = sP[cur * ST_F4 + wid * 64 + lane];
            const float4 pB = sP[cur * ST_F4 + wid * 64 + lane + 32];

            float s2k = 0.f, s6k = 0.f;
            float4 t3A, t3B;
#define PROC(kc, pc, ic, outc)                                      \
            {                                                       \
                float tk = (fmaxf(kc + pc, 0.f) + 1e-6f) * ic;      \
                s2k += tk * tk;                                     \
                float tk3 = tk * tk * tk; s6k += tk3 * tk3;         \
                outc = tk3;                                         \
            }
            PROC(kA.x, pA.x, iscA.x, t3A.x)
            PROC(kA.y, pA.y, iscA.y, t3A.y)
            PROC(kA.z, pA.z, iscA.z, t3A.z)
            PROC(kA.w, pA.w, iscA.w, t3A.w)
            PROC(kB.x, pB.x, iscB.x, t3B.x)
            PROC(kB.y, pB.y, iscB.y, t3B.y)
            PROC(kB.z, pB.z, iscB.z, t3B.z)
            PROC(kB.w, pB.w, iscB.w, t3B.w)
#undef PROC

#pragma unroll
            for (int off = 16; off; off >>= 1) {
                s2k += __shfl_xor_sync(0xffffffffu, s2k, off);
                s6k += __shfl_xor_sync(0xffffffffu, s6k, off);
            }
            const float ak = sqrtf(s2k / s6k);

            sK[cur * ST_F4 + wid * 64 + lane] =
                make_float4(t3A.x * ak, t3A.y * ak, t3A.z * ak, t3A.w * ak);
            sK[cur * ST_F4 + wid * 64 + lane + 32] =
                make_float4(t3B.x * ak, t3B.y * ak, t3B.z * ak, t3B.w * ak);
        }
        __syncthreads();

#pragma unroll
        for (int c = 0; c < 2; ++c) {
            float kd[8];
#pragma unroll
            for (int t8 = 0; t8 < 8; ++t8) {
                const int tok = c * 8 + t8;
                kd[t8] = ((const float*)(sK + cur * ST_F4 + tok * 64))[h * HD + d];
                accs += kd[t8];
            }
#pragma unroll
            for (int t8 = 0; t8 < 8; ++t8) {
                const int tok = c * 8 + t8;
                const float2 kd2 = make_float2(kd[t8], kd[t8]);
                const float4* vv = sV + cur * ST_F4 + tok * 64 + h * 8 + half * 4;
#pragma unroll
                for (int e4 = 0; e4 < 4; ++e4) {
                    const float4 v = vv[e4];
                    acc2[e4 * 2 + 0] = ffma2(kd2, make_float2(v.x, v.y), acc2[e4 * 2 + 0]);
                    acc2[e4 * 2 + 1] = ffma2(kd2, make_float2(v.z, v.w), acc2[e4 * 2 + 1]);
                }
            }
        }
        __syncthreads();                          // release buf[cur] for restage
    }
#undef STAGE

    float4* dst = (float4*)&g_part[((((size_t)bx * NB + b) * NHEAD + h) * HD + d) * HD + half * 16];
#pragma unroll
    for (int e4 = 0; e4 < 4; ++e4)
        dst[e4] = make_float4(acc2[e4 * 2].x, acc2[e4 * 2].y,
                              acc2[e4 * 2 + 1].x, acc2[e4 * 2 + 1].y);
    if (half == 0)
        g_parts[(((size_t)bx * NB + b) * NHEAD + h) * HD + d] = accs;
}

// ---------------------------------------------------------------------------
// k_reduce: sum NPART partials -> g_kv, g_ksum. Fully unrolled (MLP 32).
// ---------------------------------------------------------------------------
__global__ __launch_bounds__(256) void k_reduce()
{
    const int tid = threadIdx.x;
    const int bh  = blockIdx.x >> 2;
    const int qtr = blockIdx.x & 3;
    const int entry = qtr * 256 + tid;

    float s = 0.f;
#pragma unroll
    for (int p = 0; p < NPART; ++p)
        s += g_part[((size_t)p * NB * NHEAD + bh) * (HD * HD) + entry];
    g_kv[(size_t)bh * HD * HD + entry] = s;

    if (qtr == 0 && tid < HD) {
        float ss = 0.f;
#pragma unroll
        for (int p = 0; p < NPART; ++p)
            ss += g_parts[((size_t)p * NB * NHEAD + bh) * HD + tid];
        g_ksum[(size_t)bh * HD + tid] = ss;
    }
}

// ---------------------------------------------------------------------------
// k_ca: FUSED conv + attention. Block = (16x16 tile, head, batch), lane = ch.
// out = bias + merged-5x5-conv(v) + z * (q3 @ kv)   — single store, no RMW.
// ---------------------------------------------------------------------------
#define QP 36
#define VT_OFF 0
#define Q3_OFF (20 * 20 * 32)                  // 12800
#define ZS_OFF (Q3_OFF + 256 * QP)             // 22016
#define KS_OFF (ZS_OFF + 256)                  // 22272
#define SMEM_CA ((KS_OFF + 32) * 4)            // 89216 B

__global__ __launch_bounds__(256, 2) void k_ca(
    const float* __restrict__ qkv,
    const float* __restrict__ scale,
    const float* __restrict__ w_v,
    const float* __restrict__ b_v,
    const float* __restrict__ w_dwc,
    const float* __restrict__ b_dwc,
    float* __restrict__ out)
{
    extern __shared__ float sm[];
    float* vt  = sm + VT_OFF;
    float* q3s = sm + Q3_OFF;
    float* zs  = sm + ZS_OFF;
    float* ks  = sm + KS_OFF;

    const int tid  = threadIdx.x;
    const int lane = tid & 31;
    const int wid  = tid >> 5;
    const int b    = blockIdx.z;
    const int h    = blockIdx.y;
    const int tile = blockIdx.x;
    const int r0 = (tile >> 2) * TILE;
    const int c0 = (tile & 3) * TILE;

    const float* vb = qkv + ((size_t)2 * NB + b) * NTOK * NC;
    const float* qb = qkv + (size_t)b * NTOK * NC;

    // Stage v tile with halo (13 predicated slots, batched LDG.128)
#pragma unroll
    for (int u = 0; u < 13; ++u) {
        const int idx = tid + u * 256;
        if (idx < 20 * 20 * 8) {
            const int e4 = idx & 7;
            const int rc = idx >> 3;
            const int col = rc % 20, row = rc / 20;
            const int gy = r0 + row - 2, gx = c0 + col - 2;
            float4 v = make_float4(0.f, 0.f, 0.f, 0.f);
            if (gy >= 0 && gy < RDIM && gx >= 0 && gx < RDIM)
                v = *(const float4*)&vb[(size_t)(gy * RDIM + gx) * NC + h * HD + e4 * 4];
            ((float4*)vt)[idx] = v;
        }
    }

    // Per-lane constants (overlap the v-tile loads above)
    float wreg[25];
#pragma unroll
    for (int t = 0; t < 25; ++t) {
        const int ky = t / 5, kx = t % 5;
        float w = w_dwc[lane * 25 + t];
        if (ky >= 1 && ky <= 3 && kx >= 1 && kx <= 3)
            w += w_v[(h * HD + lane) * 9 + (ky - 1) * 3 + (kx - 1)];
        wreg[t] = w;
    }
    const float my_isc  = 1.f / log1pf(expf(scale[h * HD + lane]));
    const float my_bias = b_v[h * HD + lane] + b_dwc[lane];

    float2 kp[16];                                 // kv column for this lane
#pragma unroll
    for (int j = 0; j < 16; ++j) {
        const float a = g_kv[(((size_t)b * NHEAD + h) * HD + 2 * j) * HD + lane];
        const float c = g_kv[(((size_t)b * NHEAD + h) * HD + 2 * j + 1) * HD + lane];
        kp[j] = make_float2(a, c);
    }
    if (tid < HD) ks[tid] = g_ksum[((size_t)b * NHEAD + h) * HD + tid];

    // Phase A: focused q3 tile (batched loads per warp-row)
#pragma unroll
    for (int ty = 0; ty < 2; ++ty) {
        const int lr = wid * 2 + ty;
        const int gy = r0 + lr;
        float qv[TILE], al[TILE];
#pragma unroll
        for (int lc = 0; lc < TILE; ++lc) {
            const int i = gy * RDIM + (c0 + lc);
            qv[lc] = qb[(size_t)i * NC + h * HD + lane];
            al[lc] = g_alpha[b * NTOK + i];
        }
#pragma unroll
        for (int lc = 0; lc < TILE; ++lc) {
            const float t = (fmaxf(qv[lc], 0.f) + 1e-6f) * my_isc;
            q3s[(lr * TILE + lc) * QP + lane] = t * t * t * al[lc];
        }
    }
    __syncthreads();

    // Phase B: z per token (thread = token), FFMA2 dot
    {
        float2 zd = make_float2(0.f, 0.f);
#pragma unroll
        for (int k4 = 0; k4 < 8; ++k4) {
            const float4 q = *(const float4*)&q3s[tid * QP + 4 * k4];
            const float4 kk = *(const float4*)&ks[4 * k4];
            zd = ffma2(make_float2(q.x, q.y), make_float2(kk.x, kk.y), zd);
            zd = ffma2(make_float2(q.z, q.w), make_float2(kk.z, kk.w), zd);
        }
        zs[tid] = 1.f / (zd.x + zd.y + 1e-6f);
    }
    __syncthreads();

    // Phase C: conv (sliding register window) + FFMA2 matvec, single store
#pragma unroll
    for (int ty = 0; ty < 2; ++ty) {
        const int lr = wid * 2 + ty;
        const int gy = r0 + lr;

        float ring[5][5];
#pragma unroll
        for (int s = 0; s < 4; ++s)
#pragma unroll
            for (int ky = 0; ky < 5; ++ky)
                ring[s][ky] = vt[((lr + ky) * 20 + s) * 32 + lane];

#pragma unroll
        for (int lc = 0; lc < TILE; ++lc) {
            const int slot = (lc + 4) % 5;
#pragma unroll
            for (int ky = 0; ky < 5; ++ky)
                ring[slot][ky] = vt[((lr + ky) * 20 + lc + 4) * 32 + lane];

            const int ltok = lr * TILE + lc;

            float2 m0 = make_float2(0.f, 0.f);
            float2 m1 = make_float2(0.f, 0.f);
#pragma unroll
            for (int k4 = 0; k4 < 8; ++k4) {
                const float4 q = *(const float4*)&q3s[ltok * QP + 4 * k4];
                m0 = ffma2(make_float2(q.x, q.y), kp[2 * k4 + 0], m0);
                m1 = ffma2(make_float2(q.z, q.w), kp[2 * k4 + 1], m1);
            }
            float accv = zs[ltok] * (m0.x + m0.y + m1.x + m1.y) + my_bias;

#pragma unroll
            for (int ky = 0; ky < 5; ++ky)
#pragma unroll
                for (int kx = 0; kx < 5; ++kx)
                    accv += ring[(lc + kx) % 5][ky] * wreg[ky * 5 + kx];

            const int i = gy * RDIM + (c0 + lc);
            out[(size_t)(b * NTOK + i) * NC + h * HD + lane] = accv;
        }
    }
}

// ---------------------------------------------------------------------------
// Launch: side stream = k_alpha (overlaps stats); main = stats -> reduce;
// join; fused k_ca writes out once.
// ---------------------------------------------------------------------------
extern "C" void kernel_launch(void* const* d_in, const int* in_sizes, int n_in,
                              void* d_out, int out_size)
{
    const float* qkv   = (const float*)d_in[0];
    const float* pos   = (const float*)d_in[1];
    const float* scale = (const float*)d_in[2];
    const float* w_v   = (const float*)d_in[3];
    const float* b_v   = (const float*)d_in[4];
    const float* w_dwc = (const float*)d_in[5];
    const float* b_dwc = (const float*)d_in[6];
    float* out = (float*)d_out;

    static cudaStream_t s2 = nullptr;
    static cudaEvent_t eFork = nullptr, eJoin = nullptr;
    if (s2 == nullptr) {
        cudaStreamCreateWithFlags(&s2, cudaStreamNonBlocking);
        cudaEventCreateWithFlags(&eFork, cudaEventDisableTiming);
        cudaEventCreateWithFlags(&eJoin, cudaEventDisableTiming);
        cudaFuncSetAttribute(k_ca, cudaFuncAttributeMaxDynamicSharedMemorySize, SMEM_CA);
        cudaFuncSetAttribute(k_stats, cudaFuncAttributeMaxDynamicSharedMemorySize, SMEM_STATS);
    }

    // Fork side branch off the capture origin
    cudaEventRecord(eFork, 0);
    cudaStreamWaitEvent(s2, eFork, 0);

    // Side branch: alpha (independent of k/v stats)
    dim3 gA(NTOK / 8, NB);
    k_alpha<<<gA, 256, 0, s2>>>(qkv, scale);
    cudaEventRecord(eJoin, s2);

    // Main branch: kv stats + reduction
    dim3 g1(NPART, NB);
    k_stats<<<g1, 512, SMEM_STATS>>>(qkv, pos, scale);
    k_reduce<<<256, 256>>>();

    // Join, then fused conv+attention
    cudaStreamWaitEvent(0, eJoin, 0);
    dim3 gc(16, NHEAD, NB);
    k_ca<<<gc, 256, SMEM_CA>>>(qkv, scale, w_v, b_v, w_dwc, b_dwc, out);
}

// round 17
// speedup vs baseline: 1.1758x; 1.1758x over previous
#include <cuda_runtime.h>
#include <math.h>
#include <stdint.h>

#define NB 8
#define NTOK 4096
#define NC 256
#define NHEAD 8
#define HD 32
#define RDIM 64
#define TILE 16
#define NPART 32

// Packed dual-fp32 FMA (sm_103a): one issue slot, two fp32 FMAs, bit-exact.
__device__ __forceinline__ float2 ffma2(float2 a, float2 b, float2 c) {
    unsigned long long A, B, C, D;
    A = *(unsigned long long*)&a;
    B = *(unsigned long long*)&b;
    C = *(unsigned long long*)&c;
    asm("fma.rn.f32x2 %0, %1, %2, %3;" : "=l"(D) : "l"(A), "l"(B), "l"(C));
    return *(float2*)&D;
}

__device__ __forceinline__ void cpasync16(void* smem_dst, const void* gsrc) {
    unsigned int s = (unsigned int)__cvta_generic_to_shared(smem_dst);
    asm volatile("cp.async.cg.shared.global [%0], [%1], 16;" :: "r"(s), "l"(gsrc) : "memory");
}

// Scratch (device globals: allocation is forbidden)
__device__ float g_part[NPART * NB * NHEAD * HD * HD];   // 8 MB partial kv
__device__ float g_parts[NPART * NB * NHEAD * HD];
__device__ float g_kv[NB * NHEAD * HD * HD];
__device__ float g_ksum[NB * NHEAD * HD];
__device__ float g_alpha[NB * NTOK];

// ---------------------------------------------------------------------------
// k_alpha: per-token focusing norm ratio for q. Warp = token.
// ---------------------------------------------------------------------------
__global__ __launch_bounds__(256) void k_alpha(
    const float* __restrict__ qkv,
    const float* __restrict__ scale)
{
    __shared__ float s_isc[NC];
    const int tid  = threadIdx.x;
    const int wid  = tid >> 5;
    const int lane = tid & 31;
    const int b    = blockIdx.y;

    s_isc[tid] = 1.f / log1pf(expf(scale[tid]));
    __syncthreads();

    const int i = blockIdx.x * 8 + wid;
    const float* qb = qkv + (size_t)b * NTOK * NC + (size_t)i * NC;

    const float4 qA = ((const float4*)qb)[lane];
    const float4 qB = ((const float4*)qb)[lane + 32];
    const float4 iA = ((const float4*)s_isc)[lane];
    const float4 iB = ((const float4*)s_isc)[lane + 32];

    float s2 = 0.f, s6 = 0.f;
#define FOC(qc, ic)                                         \
    {                                                       \
        float t = (fmaxf(qc, 0.f) + 1e-6f) * ic;            \
        s2 += t * t;                                        \
        float tc = t * t * t; s6 += tc * tc;                \
    }
    FOC(qA.x, iA.x) FOC(qA.y, iA.y) FOC(qA.z, iA.z) FOC(qA.w, iA.w)
    FOC(qB.x, iB.x) FOC(qB.y, iB.y) FOC(qB.z, iB.z) FOC(qB.w, iB.w)
#undef FOC

#pragma unroll
    for (int off = 16; off; off >>= 1) {
        s2 += __shfl_xor_sync(0xffffffffu, s2, off);
        s6 += __shfl_xor_sync(0xffffffffu, s6, off);
    }
    if (lane == 0) g_alpha[b * NTOK + i] = sqrtf(s2 / s6);
}

// ---------------------------------------------------------------------------
// k_stats: cp.async double-buffered pipeline, partial outputs (R12/R14).
// ---------------------------------------------------------------------------
#define ST_F4   1024                    // float4 per array per buffer (16 tok x 64)
#define SMEM_STATS ((6 * ST_F4 + 64) * 16)   // 2 bufs x 3 arrays + isc = 99328 B

__global__ __launch_bounds__(512, 2) void k_stats(
    const float* __restrict__ qkv,
    const float* __restrict__ pos,
    const float* __restrict__ scale)
{
    extern __shared__ float4 smem4[];
    float4* sK = smem4;                  // [2][ST_F4]  (k3 written in place)
    float4* sP = smem4 + 2 * ST_F4;
    float4* sV = smem4 + 4 * ST_F4;
    float*  s_isc = (float*)(smem4 + 6 * ST_F4);

    const int tid  = threadIdx.x;
    const int wid  = tid >> 5;
    const int lane = tid & 31;
    const int b    = blockIdx.y;
    const int bx   = blockIdx.x;

    if (tid < NC) s_isc[tid] = 1.f / log1pf(expf(scale[tid]));

    const float* kb = qkv + ((size_t)NB + b) * NTOK * NC;
    const float* vb = qkv + ((size_t)2 * NB + b) * NTOK * NC;

    const int h    = wid >> 1;
    const int half = wid & 1;
    const int d    = lane;

    float2 acc2[8];
#pragma unroll
    for (int e = 0; e < 8; ++e) acc2[e] = make_float2(0.f, 0.f);
    float accs = 0.f;

    const int i0 = bx * (NTOK / NPART);          // 128 tokens per block

#define STAGE(it, bufi)                                                     \
    {                                                                       \
        _Pragma("unroll")                                                   \
        for (int u = 0; u < 2; ++u) {                                       \
            const int idx = tid + u * 512;                                  \
            const int row = idx >> 6, col4 = idx & 63;                      \
            const size_t g = (size_t)(i0 + (it) * 16 + row) * NC + col4 * 4;\
            cpasync16(&sK[(bufi) * ST_F4 + idx], kb + g);                   \
            cpasync16(&sP[(bufi) * ST_F4 + idx], pos + g);                  \
            cpasync16(&sV[(bufi) * ST_F4 + idx], vb + g);                   \
        }                                                                   \
        asm volatile("cp.async.commit_group;" ::: "memory");                \
    }

    STAGE(0, 0)
    __syncthreads();                              // s_isc visible
    const float4 iscA = ((const float4*)s_isc)[lane];
    const float4 iscB = ((const float4*)s_isc)[lane + 32];

    for (int it = 0; it < 8; ++it) {
        const int cur = it & 1;
        if (it < 7) {
            STAGE(it + 1, cur ^ 1)
            asm volatile("cp.async.wait_group 1;" ::: "memory");
        } else {
            asm volatile("cp.async.wait_group 0;" ::: "memory");
        }
        __syncthreads();                          // staged data visible to all

        {
            const float4 kA = sK[cur * ST_F4 + wid * 64 + lane];
            const float4 kB = sK[cur * ST_F4 + wid * 64 + lane + 32];
            const float4 pA = sP[cur * ST_F4 + wid * 64 + lane];
            const float4 pB = sP[cur * ST_F4 + wid * 64 + lane + 32];

            float s2k = 0.f, s6k = 0.f;
            float4 t3A, t3B;
#define PROC(kc, pc, ic, outc)                                      \
            {                                                       \
                float tk = (fmaxf(kc + pc, 0.f) + 1e-6f) * ic;      \
                s2k += tk * tk;                                     \
                float tk3 = tk * tk * tk; s6k += tk3 * tk3;         \
                outc = tk3;                                         \
            }
            PROC(kA.x, pA.x, iscA.x, t3A.x)
            PROC(kA.y, pA.y, iscA.y, t3A.y)
            PROC(kA.z, pA.z, iscA.z, t3A.z)
            PROC(kA.w, pA.w, iscA.w, t3A.w)
            PROC(kB.x, pB.x, iscB.x, t3B.x)
            PROC(kB.y, pB.y, iscB.y, t3B.y)
            PROC(kB.z, pB.z, iscB.z, t3B.z)
            PROC(kB.w, pB.w, iscB.w, t3B.w)
#undef PROC

#pragma unroll
            for (int off = 16; off; off >>= 1) {
                s2k += __shfl_xor_sync(0xffffffffu, s2k, off);
                s6k += __shfl_xor_sync(0xffffffffu, s6k, off);
            }
            const float ak = sqrtf(s2k / s6k);

            sK[cur * ST_F4 + wid * 64 + lane] =
                make_float4(t3A.x * ak, t3A.y * ak, t3A.z * ak, t3A.w * ak);
            sK[cur * ST_F4 + wid * 64 + lane + 32] =
                make_float4(t3B.x * ak, t3B.y * ak, t3B.z * ak, t3B.w * ak);
        }
        __syncthreads();

#pragma unroll
        for (int c = 0; c < 2; ++c) {
            float kd[8];
#pragma unroll
            for (int t8 = 0; t8 < 8; ++t8) {
                const int tok = c * 8 + t8;
                kd[t8] = ((const float*)(sK + cur * ST_F4 + tok * 64))[h * HD + d];
                accs += kd[t8];
            }
#pragma unroll
            for (int t8 = 0; t8 < 8; ++t8) {
                const int tok = c * 8 + t8;
                const float2 kd2 = make_float2(kd[t8], kd[t8]);
                const float4* vv = sV + cur * ST_F4 + tok * 64 + h * 8 + half * 4;
#pragma unroll
                for (int e4 = 0; e4 < 4; ++e4) {
                    const float4 v = vv[e4];
                    acc2[e4 * 2 + 0] = ffma2(kd2, make_float2(v.x, v.y), acc2[e4 * 2 + 0]);
                    acc2[e4 * 2 + 1] = ffma2(kd2, make_float2(v.z, v.w), acc2[e4 * 2 + 1]);
                }
            }
        }
        __syncthreads();                          // release buf[cur] for restage
    }
#undef STAGE

    float4* dst = (float4*)&g_part[((((size_t)bx * NB + b) * NHEAD + h) * HD + d) * HD + half * 16];
#pragma unroll
    for (int e4 = 0; e4 < 4; ++e4)
        dst[e4] = make_float4(acc2[e4 * 2].x, acc2[e4 * 2].y,
                              acc2[e4 * 2 + 1].x, acc2[e4 * 2 + 1].y);
    if (half == 0)
        g_parts[(((size_t)bx * NB + b) * NHEAD + h) * HD + d] = accs;
}

// ---------------------------------------------------------------------------
// k_reduce v2: 2 threads per entry (16 partials each, fixed order), smem
// combine. Grid 512 = (bh 64 x oct 8); block 256 covers 128 entries.
// ---------------------------------------------------------------------------
__global__ __launch_bounds__(256) void k_reduce()
{
    __shared__ float s_half[128];
    const int bh  = blockIdx.x >> 3;
    const int oct = blockIdx.x & 7;
    const int tid = threadIdx.x;
    const int el  = tid & 127;                    // entry-local
    const int hp  = tid >> 7;                     // which 16-partial half
    const int e   = oct * 128 + el;               // entry within bh (0..1023)

    float s = 0.f;
#pragma unroll
    for (int p = 0; p < 16; ++p)
        s += g_part[((size_t)(hp * 16 + p) * NB * NHEAD + bh) * (HD * HD) + e];

    if (hp == 1) s_half[el] = s;
    __syncthreads();
    if (hp == 0)
        g_kv[(size_t)bh * HD * HD + e] = s + s_half[el];

    if (oct == 0 && hp == 0 && tid < HD) {
        float ss = 0.f;
#pragma unroll
        for (int p = 0; p < NPART; ++p)
            ss += g_parts[((size_t)p * NB * NHEAD + bh) * HD + tid];
        g_ksum[(size_t)bh * HD + tid] = ss;
    }
}

// ---------------------------------------------------------------------------
// k_conv: merged 5x5 depthwise conv (LePE folded in) + bias -> writes out.
// ---------------------------------------------------------------------------
__global__ __launch_bounds__(256, 3) void k_conv(
    const float* __restrict__ qkv,
    const float* __restrict__ w_v,
    const float* __restrict__ b_v,
    const float* __restrict__ w_dwc,
    const float* __restrict__ b_dwc,
    float* __restrict__ out)
{
    extern __shared__ float vt[];                 // [20][20][32]

    const int tid  = threadIdx.x;
    const int lane = tid & 31;
    const int wid  = tid >> 5;
    const int b    = blockIdx.z;
    const int h    = blockIdx.y;
    const int tile = blockIdx.x;
    const int r0 = (tile >> 2) * TILE;
    const int c0 = (tile & 3) * TILE;

    const float* vb = qkv + ((size_t)2 * NB + b) * NTOK * NC;

#pragma unroll
    for (int u = 0; u < 13; ++u) {
        const int idx = tid + u * 256;
        if (idx < 20 * 20 * 8) {
            const int e4 = idx & 7;
            const int rc = idx >> 3;
            const int col = rc % 20, row = rc / 20;
            const int gy = r0 + row - 2, gx = c0 + col - 2;
            float4 v = make_float4(0.f, 0.f, 0.f, 0.f);
            if (gy >= 0 && gy < RDIM && gx >= 0 && gx < RDIM)
                v = *(const float4*)&vb[(size_t)(gy * RDIM + gx) * NC + h * HD + e4 * 4];
            ((float4*)vt)[idx] = v;
        }
    }

    float wreg[25];
#pragma unroll
    for (int t = 0; t < 25; ++t) {
        const int ky = t / 5, kx = t % 5;
        float w = w_dwc[lane * 25 + t];
        if (ky >= 1 && ky <= 3 && kx >= 1 && kx <= 3)
            w += w_v[(h * HD + lane) * 9 + (ky - 1) * 3 + (kx - 1)];
        wreg[t] = w;
    }
    const float my_bias = b_v[h * HD + lane] + b_dwc[lane];
    __syncthreads();

#pragma unroll
    for (int ty = 0; ty < 2; ++ty) {
        const int lr = wid * 2 + ty;
        const int gy = r0 + lr;

        float ring[5][5];
#pragma unroll
        for (int s = 0; s < 4; ++s)
#pragma unroll
            for (int ky = 0; ky < 5; ++ky)
                ring[s][ky] = vt[((lr + ky) * 20 + s) * 32 + lane];

#pragma unroll
        for (int lc = 0; lc < TILE; ++lc) {
            const int slot = (lc + 4) % 5;
#pragma unroll
            for (int ky = 0; ky < 5; ++ky)
                ring[slot][ky] = vt[((lr + ky) * 20 + lc + 4) * 32 + lane];

            float accv = my_bias;
#pragma unroll
            for (int ky = 0; ky < 5; ++ky)
#pragma unroll
                for (int kx = 0; kx < 5; ++kx)
                    accv += ring[(lc + kx) % 5][ky] * wreg[ky * 5 + kx];

            const int i = gy * RDIM + (c0 + lc);
            out[(size_t)(b * NTOK + i) * NC + h * HD + lane] = accv;
        }
    }
}

// ---------------------------------------------------------------------------
// k_attn: out += z * (q3 @ kv). FFMA2 matvec. Grid (16, NHEAD, NB):
// block = 256 tokens of one head. Phase C: 8 chunks of 4 tokens with
// one-chunk-ahead ov prefetch (register-neutral software pipeline).
// ---------------------------------------------------------------------------
#define QP 36

__global__ __launch_bounds__(256, 4) void k_attn(
    const float* __restrict__ qkv,
    const float* __restrict__ scale,
    float* __restrict__ out)
{
    __shared__ float q3s[256 * QP];
    __shared__ float a_s[256];
    __shared__ float zs[256];
    __shared__ float ks[HD];

    const int tid  = threadIdx.x;
    const int lane = tid & 31;
    const int wid  = tid >> 5;
    const int b    = blockIdx.z;
    const int h    = blockIdx.y;
    const int s0   = blockIdx.x * 256;

    const float* qb = qkv + (size_t)b * NTOK * NC;

    // kv column for this lane, packed into 16 float2 pairs (d, d+1)
    float2 kp[16];
#pragma unroll
    for (int j = 0; j < 16; ++j) {
        const float a = g_kv[(((size_t)b * NHEAD + h) * HD + 2 * j) * HD + lane];
        const float c = g_kv[(((size_t)b * NHEAD + h) * HD + 2 * j + 1) * HD + lane];
        kp[j] = make_float2(a, c);
    }
    const float my_isc = 1.f / log1pf(expf(scale[h * HD + lane]));
    if (tid < HD) ks[tid] = g_ksum[((size_t)b * NHEAD + h) * HD + tid];

    a_s[tid] = g_alpha[b * NTOK + s0 + tid];
    __syncthreads();

    // Phase A: focused q3 (batched LDGs)
#pragma unroll
    for (int c = 0; c < 2; ++c) {
        float qv[16];
#pragma unroll
        for (int j = 0; j < 16; ++j) {
            const int lt = wid * 32 + c * 16 + j;
            qv[j] = qb[(size_t)(s0 + lt) * NC + h * HD + lane];
        }
#pragma unroll
        for (int j = 0; j < 16; ++j) {
            const int lt = wid * 32 + c * 16 + j;
            const float t = (fmaxf(qv[j], 0.f) + 1e-6f) * my_isc;
            q3s[lt * QP + lane] = t * t * t * a_s[lt];
        }
    }
    __syncthreads();

    // Phase B: z per token (thread = token), FFMA2 dot
    {
        float2 zd = make_float2(0.f, 0.f);
#pragma unroll
        for (int k4 = 0; k4 < 8; ++k4) {
            const float4 q = *(const float4*)&q3s[tid * QP + 4 * k4];
            const float4 kk = *(const float4*)&ks[4 * k4];
            zd = ffma2(make_float2(q.x, q.y), make_float2(kk.x, kk.y), zd);
            zd = ffma2(make_float2(q.z, q.w), make_float2(kk.z, kk.w), zd);
        }
        zs[tid] = 1.f / (zd.x + zd.y + 1e-6f);
    }
    __syncthreads();

    // Phase C: FFMA2 matvec + RMW, 8 chunks of 4 with ov prefetch pipeline
    {
        float ov[4], nv[4];
#pragma unroll
        for (int j = 0; j < 4; ++j)
            ov[j] = out[(size_t)(b * NTOK + s0 + wid * 32 + j) * NC + h * HD + lane];

#pragma unroll
        for (int c = 0; c < 8; ++c) {
            if (c < 7) {
#pragma unroll
                for (int j = 0; j < 4; ++j) {
                    const int lt = wid * 32 + (c + 1) * 4 + j;
                    nv[j] = out[(size_t)(b * NTOK + s0 + lt) * NC + h * HD + lane];
                }
            }
#pragma unroll
            for (int j = 0; j < 4; ++j) {
                const int lt = wid * 32 + c * 4 + j;
                float2 m0 = make_float2(0.f, 0.f);
                float2 m1 = make_float2(0.f, 0.f);
#pragma unroll
                for (int k4 = 0; k4 < 8; ++k4) {
                    const float4 q = *(const float4*)&q3s[lt * QP + 4 * k4];
                    m0 = ffma2(make_float2(q.x, q.y), kp[2 * k4 + 0], m0);
                    m1 = ffma2(make_float2(q.z, q.w), kp[2 * k4 + 1], m1);
                }
                out[(size_t)(b * NTOK + s0 + lt) * NC + h * HD + lane] =
                    ov[j] + zs[lt] * (m0.x + m0.y + m1.x + m1.y);
            }
#pragma unroll
            for (int j = 0; j < 4; ++j) ov[j] = nv[j];
        }
    }
}

// ---------------------------------------------------------------------------
// Launch: proven R7/R14 two-branch graph.
//   main stream:  k_stats -> k_reduce ──┐
//   side stream:  k_alpha -> k_conv  ───┴─> k_attn
// ---------------------------------------------------------------------------
extern "C" void kernel_launch(void* const* d_in, const int* in_sizes, int n_in,
                              void* d_out, int out_size)
{
    const float* qkv   = (const float*)d_in[0];
    const float* pos   = (const float*)d_in[1];
    const float* scale = (const float*)d_in[2];
    const float* w_v   = (const float*)d_in[3];
    const float* b_v   = (const float*)d_in[4];
    const float* w_dwc = (const float*)d_in[5];
    const float* b_dwc = (const float*)d_in[6];
    float* out = (float*)d_out;

    static cudaStream_t s2 = nullptr;
    static cudaEvent_t eFork = nullptr, eJoin = nullptr;
    if (s2 == nullptr) {
        cudaStreamCreateWithFlags(&s2, cudaStreamNonBlocking);
        cudaEventCreateWithFlags(&eFork, cudaEventDisableTiming);
        cudaEventCreateWithFlags(&eJoin, cudaEventDisableTiming);
        const int smem_conv = 20 * 20 * 32 * sizeof(float);
        cudaFuncSetAttribute(k_conv, cudaFuncAttributeMaxDynamicSharedMemorySize, smem_conv);
        cudaFuncSetAttribute(k_stats, cudaFuncAttributeMaxDynamicSharedMemorySize, SMEM_STATS);
    }
    const int smem_conv = 20 * 20 * 32 * sizeof(float);

    // Fork side branch off the capture origin
    cudaEventRecord(eFork, 0);
    cudaStreamWaitEvent(s2, eFork, 0);

    // Side branch: alpha + conv (independent of k/v stats)
    dim3 gA(NTOK / 8, NB);
    k_alpha<<<gA, 256, 0, s2>>>(qkv, scale);
    dim3 gc(16, NHEAD, NB);
    k_conv<<<gc, 256, smem_conv, s2>>>(qkv, w_v, b_v, w_dwc, b_dwc, out);
    cudaEventRecord(eJoin, s2);

    // Main branch: kv stats + reduction
    dim3 g1(NPART, NB);
    k_stats<<<g1, 512, SMEM_STATS>>>(qkv, pos, scale);
    k_reduce<<<512, 256>>>();

    // Join, then attention RMW
    cudaStreamWaitEvent(0, eJoin, 0);
    dim3 ga(16, NHEAD, NB);
    k_attn<<<ga, 256>>>(qkv, scale, out);
}